// round 1
// baseline (speedup 1.0000x reference)
#include <cuda_runtime.h>
#include <math.h>
#include <float.h>

// Problem constants (shapes fixed by setup_inputs)
#define D_DIM 640
#define D4    160          // D_DIM / 4
#define S_SHOT 5
#define W_WAY  5
#define TOPK   8
#define M_MAX  50000
#define NS_MAX (M_MAX + S_SHOT)

// Static device scratch (no allocations allowed)
__device__ float g_q[W_WAY * D_DIM];          // mean of normalized support per way
__device__ float g_sim[W_WAY * NS_MAX];       // sim[w][m], m<5 = support part
__device__ float g_topv[W_WAY * TOPK];
__device__ int   g_topi[W_WAY * TOPK];

// ---------------------------------------------------------------------------
// Kernel 1: norms of 25 support vectors, q[w] = mean_s(support_hat[s,w]),
// and the 25 support self-similarities sim[w][m], m in [0,5).
// ---------------------------------------------------------------------------
__global__ void prep_kernel(const float* __restrict__ sup) {
    __shared__ float s_inv[S_SHOT * W_WAY];
    __shared__ float s_q[W_WAY * D_DIM];
    int tid = threadIdx.x, wid = tid >> 5, lane = tid & 31;
    int nw = blockDim.x >> 5;

    // Phase 1: inverse norms of each support[s,w,:]
    for (int v = wid; v < S_SHOT * W_WAY; v += nw) {
        int s = v / W_WAY, w = v % W_WAY;
        const float* p = sup + (s * W_WAY + w) * D_DIM;
        float ss = 0.f;
        for (int i = lane; i < D_DIM; i += 32) { float x = p[i]; ss += x * x; }
        #pragma unroll
        for (int o = 16; o; o >>= 1) ss += __shfl_down_sync(0xffffffffu, ss, o);
        if (lane == 0) s_inv[v] = 1.0f / fmaxf(sqrtf(ss), 1e-12f);
    }
    __syncthreads();

    // Phase 2: q[w][d]
    for (int i = tid; i < W_WAY * D_DIM; i += blockDim.x) {
        int w = i / D_DIM, d = i - w * D_DIM;
        float acc = 0.f;
        #pragma unroll
        for (int s = 0; s < S_SHOT; ++s)
            acc += sup[(s * W_WAY + w) * D_DIM + d] * s_inv[s * W_WAY + w];
        float qv = acc * (1.0f / (float)S_SHOT);
        s_q[i] = qv;
        g_q[i] = qv;
    }
    __syncthreads();

    // Phase 3: sim[w][m] for support part
    for (int v = wid; v < W_WAY * S_SHOT; v += nw) {
        int w = v / S_SHOT, m = v % S_SHOT;
        const float* p = sup + (m * W_WAY + w) * D_DIM;
        float dpv = 0.f;
        for (int i = lane; i < D_DIM; i += 32) dpv += s_q[w * D_DIM + i] * p[i];
        #pragma unroll
        for (int o = 16; o; o >>= 1) dpv += __shfl_down_sync(0xffffffffu, dpv, o);
        if (lane == 0) g_sim[w * NS_MAX + m] = dpv * s_inv[m * W_WAY + w];
    }
}

// ---------------------------------------------------------------------------
// Kernel 2: the 128 MB pass. One warp handles 4 memory rows at a time:
// per row, 5 query dots + self-dot, then normalize and write sim.
// ---------------------------------------------------------------------------
__global__ void sim_kernel(const float* __restrict__ mem, int M) {
    __shared__ float4 s_q[W_WAY * D4];   // 12.8 KB
    int tid = threadIdx.x;
    const float4* q4 = reinterpret_cast<const float4*>(g_q);
    for (int i = tid; i < W_WAY * D4; i += blockDim.x) s_q[i] = q4[i];
    __syncthreads();

    int wid = tid >> 5, lane = tid & 31;
    int wpb = blockDim.x >> 5;
    int nwarps = gridDim.x * wpb;
    int groups = (M + 3) >> 2;
    const float4* base = reinterpret_cast<const float4*>(mem);

    for (int g = blockIdx.x * wpb + wid; g < groups; g += nwarps) {
        int row0 = g << 2;
        const float4* p = base + (size_t)row0 * D4;

        if (row0 + 4 <= M) {
            float ss0 = 0.f, ss1 = 0.f, ss2 = 0.f, ss3 = 0.f;
            float dp[W_WAY][4];
            #pragma unroll
            for (int w = 0; w < W_WAY; ++w) {
                dp[w][0] = 0.f; dp[w][1] = 0.f; dp[w][2] = 0.f; dp[w][3] = 0.f;
            }
            #pragma unroll
            for (int i = 0; i < 5; ++i) {
                int idx = lane + (i << 5);
                float4 v0 = p[idx];
                float4 v1 = p[D4 + idx];
                float4 v2 = p[2 * D4 + idx];
                float4 v3 = p[3 * D4 + idx];
                ss0 += v0.x * v0.x + v0.y * v0.y + v0.z * v0.z + v0.w * v0.w;
                ss1 += v1.x * v1.x + v1.y * v1.y + v1.z * v1.z + v1.w * v1.w;
                ss2 += v2.x * v2.x + v2.y * v2.y + v2.z * v2.z + v2.w * v2.w;
                ss3 += v3.x * v3.x + v3.y * v3.y + v3.z * v3.z + v3.w * v3.w;
                #pragma unroll
                for (int w = 0; w < W_WAY; ++w) {
                    float4 a = s_q[w * D4 + idx];
                    dp[w][0] += v0.x * a.x + v0.y * a.y + v0.z * a.z + v0.w * a.w;
                    dp[w][1] += v1.x * a.x + v1.y * a.y + v1.z * a.z + v1.w * a.w;
                    dp[w][2] += v2.x * a.x + v2.y * a.y + v2.z * a.z + v2.w * a.w;
                    dp[w][3] += v3.x * a.x + v3.y * a.y + v3.z * a.z + v3.w * a.w;
                }
            }
            // warp-reduce 24 accumulators
            #pragma unroll
            for (int o = 16; o; o >>= 1) {
                ss0 += __shfl_down_sync(0xffffffffu, ss0, o);
                ss1 += __shfl_down_sync(0xffffffffu, ss1, o);
                ss2 += __shfl_down_sync(0xffffffffu, ss2, o);
                ss3 += __shfl_down_sync(0xffffffffu, ss3, o);
                #pragma unroll
                for (int w = 0; w < W_WAY; ++w) {
                    dp[w][0] += __shfl_down_sync(0xffffffffu, dp[w][0], o);
                    dp[w][1] += __shfl_down_sync(0xffffffffu, dp[w][1], o);
                    dp[w][2] += __shfl_down_sync(0xffffffffu, dp[w][2], o);
                    dp[w][3] += __shfl_down_sync(0xffffffffu, dp[w][3], o);
                }
            }
            if (lane == 0) {
                float i0 = 1.0f / fmaxf(sqrtf(ss0), 1e-12f);
                float i1 = 1.0f / fmaxf(sqrtf(ss1), 1e-12f);
                float i2 = 1.0f / fmaxf(sqrtf(ss2), 1e-12f);
                float i3 = 1.0f / fmaxf(sqrtf(ss3), 1e-12f);
                #pragma unroll
                for (int w = 0; w < W_WAY; ++w) {
                    float* o = g_sim + w * NS_MAX + S_SHOT + row0;
                    o[0] = dp[w][0] * i0;
                    o[1] = dp[w][1] * i1;
                    o[2] = dp[w][2] * i2;
                    o[3] = dp[w][3] * i3;
                }
            }
        } else {
            // tail (unused when M % 4 == 0)
            for (int r = 0; row0 + r < M; ++r) {
                float ssl = 0.f;
                float dpl[W_WAY] = {0.f, 0.f, 0.f, 0.f, 0.f};
                #pragma unroll
                for (int i = 0; i < 5; ++i) {
                    int idx = lane + (i << 5);
                    float4 v = p[r * D4 + idx];
                    ssl += v.x * v.x + v.y * v.y + v.z * v.z + v.w * v.w;
                    #pragma unroll
                    for (int w = 0; w < W_WAY; ++w) {
                        float4 a = s_q[w * D4 + idx];
                        dpl[w] += v.x * a.x + v.y * a.y + v.z * a.z + v.w * a.w;
                    }
                }
                #pragma unroll
                for (int o = 16; o; o >>= 1) {
                    ssl += __shfl_down_sync(0xffffffffu, ssl, o);
                    #pragma unroll
                    for (int w = 0; w < W_WAY; ++w)
                        dpl[w] += __shfl_down_sync(0xffffffffu, dpl[w], o);
                }
                if (lane == 0) {
                    float inv = 1.0f / fmaxf(sqrtf(ssl), 1e-12f);
                    #pragma unroll
                    for (int w = 0; w < W_WAY; ++w)
                        g_sim[w * NS_MAX + S_SHOT + row0 + r] = dpl[w] * inv;
                }
            }
        }
    }
}

// ---------------------------------------------------------------------------
// Kernel 3: top-8 per way. Per-thread sorted-8 list (registers, unrolled
// insertion) then shared-memory tree merge with lower-index tie-break.
// ---------------------------------------------------------------------------
#define TK_THREADS 256

#define INS(J) do {                                        \
    _Pragma("unroll")                                      \
    for (int kk = TOPK - 1; kk > (J); --kk) {              \
        av[kk] = av[kk - 1]; ai[kk] = ai[kk - 1];          \
    }                                                      \
    av[J] = x; ai[J] = i;                                  \
} while (0)

__global__ void topk_kernel(int M) {
    __shared__ float sv[TK_THREADS * TOPK];
    __shared__ int   si[TK_THREADS * TOPK];
    int w = blockIdx.x;
    int NS = M + S_SHOT;
    int tid = threadIdx.x;
    const float* sim = g_sim + w * NS_MAX;

    float av[TOPK]; int ai[TOPK];
    #pragma unroll
    for (int k = 0; k < TOPK; ++k) { av[k] = -FLT_MAX; ai[k] = 0x7fffffff; }

    // strictly-greater insert => on ties the earlier (lower) index is kept
    for (int i = tid; i < NS; i += TK_THREADS) {
        float x = sim[i];
        if (x > av[7]) {
            if (x > av[3]) {
                if (x > av[1]) { if (x > av[0]) INS(0); else INS(1); }
                else           { if (x > av[2]) INS(2); else INS(3); }
            } else {
                if (x > av[5]) { if (x > av[4]) INS(4); else INS(5); }
                else           { if (x > av[6]) INS(6); else INS(7); }
            }
        }
    }

    #pragma unroll
    for (int k = 0; k < TOPK; ++k) { sv[tid * TOPK + k] = av[k]; si[tid * TOPK + k] = ai[k]; }

    for (int stride = TK_THREADS >> 1; stride >= 1; stride >>= 1) {
        __syncthreads();
        if (tid < stride) {
            float la[TOPK], lb[TOPK], ov[TOPK];
            int   lia[TOPK], lib[TOPK], oi[TOPK];
            #pragma unroll
            for (int k = 0; k < TOPK; ++k) {
                la[k]  = sv[tid * TOPK + k];            lia[k] = si[tid * TOPK + k];
                lb[k]  = sv[(tid + stride) * TOPK + k]; lib[k] = si[(tid + stride) * TOPK + k];
            }
            int pa = 0, pb = 0;
            #pragma unroll
            for (int k = 0; k < TOPK; ++k) {
                bool takeA = (la[pa] > lb[pb]) ||
                             (la[pa] == lb[pb] && lia[pa] <= lib[pb]);
                if (takeA) { ov[k] = la[pa]; oi[k] = lia[pa]; ++pa; }
                else       { ov[k] = lb[pb]; oi[k] = lib[pb]; ++pb; }
            }
            #pragma unroll
            for (int k = 0; k < TOPK; ++k) { sv[tid * TOPK + k] = ov[k]; si[tid * TOPK + k] = oi[k]; }
        }
    }
    if (tid == 0) {
        #pragma unroll
        for (int k = 0; k < TOPK; ++k) {
            g_topv[w * TOPK + k] = sv[k];
            g_topi[w * TOPK + k] = si[k];
        }
    }
}

// ---------------------------------------------------------------------------
// Kernel 4: out[w][d] = sum_k wt_k * row(ind_k)[d] / sum_k wt_k
// row(m) = support[m, w, :] if m < 5 else memory[m-5, :]
// ---------------------------------------------------------------------------
__global__ void out_kernel(const float* __restrict__ sup,
                           const float* __restrict__ mem,
                           float* __restrict__ out) {
    int w = blockIdx.x;
    __shared__ float wt[TOPK];
    __shared__ const float* rowp[TOPK];
    if (threadIdx.x < TOPK) {
        int k = threadIdx.x;
        wt[k] = g_topv[w * TOPK + k];
        int m = g_topi[w * TOPK + k];
        rowp[k] = (m < S_SHOT) ? (sup + (m * W_WAY + w) * D_DIM)
                               : (mem + (size_t)(m - S_SHOT) * D_DIM);
    }
    __syncthreads();
    float den = 0.f;
    #pragma unroll
    for (int k = 0; k < TOPK; ++k) den += wt[k];

    for (int d = threadIdx.x; d < D_DIM; d += blockDim.x) {
        float acc = 0.f;
        #pragma unroll
        for (int k = 0; k < TOPK; ++k) acc += wt[k] * rowp[k][d];
        out[w * D_DIM + d] = acc / den;
    }
}

// ---------------------------------------------------------------------------
extern "C" void kernel_launch(void* const* d_in, const int* in_sizes, int n_in,
                              void* d_out, int out_size) {
    const float* sup = (const float*)d_in[0];   // [1,5,5,640]
    const float* mem = (const float*)d_in[1];   // [M,640]
    float* out = (float*)d_out;                 // [1,5,640]

    int M = in_sizes[1] / D_DIM;
    if (M > M_MAX) M = M_MAX;

    prep_kernel<<<1, 256>>>(sup);
    sim_kernel<<<1184, 256>>>(mem, M);
    topk_kernel<<<W_WAY, TK_THREADS>>>(M);
    out_kernel<<<W_WAY, 256>>>(sup, mem, out);
}